// round 9
// baseline (speedup 1.0000x reference)
#include <cuda_runtime.h>
#include <cuda_fp16.h>

#define EMBED 128
#define ATTR 25
#define REM 28
#define NLEVEL 50
#define NCOMB 240                    // 2*2*3*20
#define NFULL (NLEVEL * NCOMB)       // 12000 full-product rows

#define WPAD 129                     // smem row pitch (floats) -> conflict-free dot reads
#define BASE_SMEM_BYTES (EMBED * WPAD * 4)   // 66048
#define ROWS_PER_BLK 10              // 29 blocks x 10 rows = 290

// Base projected tables (fp32, exact)
__device__ float g_Lrow[NLEVEL * EMBED];
__device__ float g_Crow[NCOMB * EMBED];
// Full product table, fp16: 12000 * 128 * 2 B = 3 MB (L2-resident)
__device__ __half g_Full[NFULL * EMBED];

// ---- Kernel A: 29 blocks x 256 threads; each block stages W once, computes 10 rows.
__global__ void __launch_bounds__(256)
base_kernel(const float* __restrict__ level_tab,
            const float* __restrict__ type_tab,
            const float* __restrict__ feature_tab,
            const float* __restrict__ exchange_tab,
            const float* __restrict__ pair_tab,
            const float* __restrict__ W,
            const float* __restrict__ b)
{
    extern __shared__ float sW[];    // sW[e*WPAD + k] = W[e][k]
    const int tid = threadIdx.x;

    // Coalesced stage: 4096 float4, 256 threads -> 16 each.
    {
        const float4* W4 = reinterpret_cast<const float4*>(W);
        #pragma unroll 4
        for (int i = tid; i < EMBED * EMBED / 4; i += 256) {
            float4 v = W4[i];
            int e = i >> 5;           // 32 float4 per W row
            int k = (i & 31) << 2;
            float* dst = sW + e * WPAD + k;
            dst[0] = v.x; dst[1] = v.y; dst[2] = v.z; dst[3] = v.w;
        }
    }
    __syncthreads();

    const int row0 = blockIdx.x * ROWS_PER_BLK;

    // 10 rows * 128 e = 1280 items; thread handles items tid, tid+256, ... (5 each).
    for (int item = tid; item < ROWS_PER_BLK * EMBED; item += 256) {
        int r = row0 + (item >> 7);   // lanes share r (fixed per 128-item group boundary-safe: 256|128)
        int e = item & 127;           // lanes span e -> sW reads conflict-free
        const float* we = sW + e * WPAD;

        if (r < NLEVEL) {
            const float* lt = level_tab + r * ATTR;
            float s0 = 0.f, s1 = 0.f, s2 = 0.f, s3 = 0.f;
            #pragma unroll
            for (int k = 0; k < 24; k += 4) {
                s0 += lt[k]     * we[k];
                s1 += lt[k + 1] * we[k + 1];
                s2 += lt[k + 2] * we[k + 2];
                s3 += lt[k + 3] * we[k + 3];
            }
            s0 += lt[24] * we[24];
            g_Lrow[r * EMBED + e] = (s0 + s1) + (s2 + s3);
        } else {
            int c = r - NLEVEL;
            int p = c % 20, x = (c / 20) % 3, f = (c / 60) % 2, t = c / 120;
            const float* tt = type_tab     + t * ATTR;
            const float* ft = feature_tab  + f * ATTR;
            const float* xt = exchange_tab + x * ATTR;
            const float* pt = pair_tab     + p * REM;
            float s0 = b[e], s1 = 0.f, s2 = 0.f, s3 = 0.f;
            #pragma unroll
            for (int k = 0; k < ATTR; k++) {
                s0 += tt[k] * we[25 + k];
                s1 += ft[k] * we[50 + k];
                s2 += xt[k] * we[75 + k];
            }
            #pragma unroll
            for (int k = 0; k < REM; k++)
                s3 += pt[k] * we[100 + k];
            g_Crow[c * EMBED + e] = (s0 + s1) + (s2 + s3);
        }
    }
}

// ---- Kernel B: expand to 12000-row fp16 full-product table (fp32 sum, one fp16 round).
__global__ void __launch_bounds__(256)
expand_kernel()
{
    const int total = NFULL * (EMBED / 2);
    __half2* full2 = reinterpret_cast<__half2*>(g_Full);
    for (int i = blockIdx.x * 256 + threadIdx.x; i < total; i += gridDim.x * 256) {
        int row = i >> 6;          // / 64
        int pos = (i & 63) << 1;
        int l = row / NCOMB;
        int c = row - l * NCOMB;
        float s0 = g_Lrow[l * EMBED + pos]     + g_Crow[c * EMBED + pos];
        float s1 = g_Lrow[l * EMBED + pos + 1] + g_Crow[c * EMBED + pos + 1];
        full2[i] = __floats2half2_rn(s0, s1);
    }
}

// ---- Kernel C: pure streaming gather (unchanged — at DRAM-write floor ~86us).
__global__ void __launch_bounds__(256, 6)
gather_kernel(const int* __restrict__ level_idx,
              const int* __restrict__ type_idx,
              const int* __restrict__ feature_idx,
              const int* __restrict__ exchange_idx,
              const int* __restrict__ pair_idx,
              float4* __restrict__ out, int n)
{
    const uint2* full2 = reinterpret_cast<const uint2*>(g_Full);
    const int lane   = threadIdx.x & 31;
    const int warp   = (blockIdx.x * 256 + threadIdx.x) >> 5;
    const int nwarps = (gridDim.x * 256) >> 5;

    int r = warp * 8;
    const int stride = nwarps * 8;

    for (; r + 7 < n; r += stride) {
        int4 L0 = *reinterpret_cast<const int4*>(level_idx + r);
        int4 L1 = *reinterpret_cast<const int4*>(level_idx + r + 4);
        int4 T0 = *reinterpret_cast<const int4*>(type_idx + r);
        int4 T1 = *reinterpret_cast<const int4*>(type_idx + r + 4);
        int4 F0 = *reinterpret_cast<const int4*>(feature_idx + r);
        int4 F1 = *reinterpret_cast<const int4*>(feature_idx + r + 4);
        int4 X0 = *reinterpret_cast<const int4*>(exchange_idx + r);
        int4 X1 = *reinterpret_cast<const int4*>(exchange_idx + r + 4);
        int4 P0 = *reinterpret_cast<const int4*>(pair_idx + r);
        int4 P1 = *reinterpret_cast<const int4*>(pair_idx + r + 4);

        int l[8] = {L0.x, L0.y, L0.z, L0.w, L1.x, L1.y, L1.z, L1.w};
        int t[8] = {T0.x, T0.y, T0.z, T0.w, T1.x, T1.y, T1.z, T1.w};
        int f[8] = {F0.x, F0.y, F0.z, F0.w, F1.x, F1.y, F1.z, F1.w};
        int x[8] = {X0.x, X0.y, X0.z, X0.w, X1.x, X1.y, X1.z, X1.w};
        int p[8] = {P0.x, P0.y, P0.z, P0.w, P1.x, P1.y, P1.z, P1.w};

        uint2 hv[8];
        #pragma unroll
        for (int k = 0; k < 8; k++) {
            int row = l[k] * NCOMB + ((t[k] * 2 + f[k]) * 3 + x[k]) * 20 + p[k];
            hv[k] = __ldg(&full2[row * 32 + lane]);
        }
        #pragma unroll
        for (int k = 0; k < 8; k++) {
            const __half2* hp = reinterpret_cast<const __half2*>(&hv[k]);
            float2 f0 = __half22float2(hp[0]);
            float2 f1 = __half22float2(hp[1]);
            float4 s;
            s.x = f0.x; s.y = f0.y; s.z = f1.x; s.w = f1.y;
            __stcs(out + (size_t)(r + k) * 32 + lane, s);
        }
    }
    for (; r < n; r++) {   // tail
        int row = level_idx[r] * NCOMB
                + ((type_idx[r] * 2 + feature_idx[r]) * 3 + exchange_idx[r]) * 20
                + pair_idx[r];
        uint2 hv = __ldg(&full2[row * 32 + lane]);
        const __half2* hp = reinterpret_cast<const __half2*>(&hv);
        float2 f0 = __half22float2(hp[0]);
        float2 f1 = __half22float2(hp[1]);
        float4 s;
        s.x = f0.x; s.y = f0.y; s.z = f1.x; s.w = f1.y;
        out[(size_t)r * 32 + lane] = s;
    }
}

extern "C" void kernel_launch(void* const* d_in, const int* in_sizes, int n_in,
                              void* d_out, int out_size) {
    const float* level_tab    = (const float*)d_in[0];
    const float* type_tab     = (const float*)d_in[1];
    const float* feature_tab  = (const float*)d_in[2];
    const float* exchange_tab = (const float*)d_in[3];
    const float* pair_tab     = (const float*)d_in[4];
    const float* W            = (const float*)d_in[5];
    const float* b            = (const float*)d_in[6];
    const int* level_idx      = (const int*)d_in[7];
    const int* type_idx       = (const int*)d_in[8];
    const int* feature_idx    = (const int*)d_in[9];
    const int* exchange_idx   = (const int*)d_in[10];
    const int* pair_idx       = (const int*)d_in[11];

    int n = in_sizes[7];   // N rows

    int sm_count = 148;
    cudaDeviceGetAttribute(&sm_count, cudaDevAttrMultiProcessorCount, 0);

    cudaFuncSetAttribute(base_kernel,
                         cudaFuncAttributeMaxDynamicSharedMemorySize, BASE_SMEM_BYTES);

    // 29 blocks x 256 threads, 10 rows per block (blocks 0-4 level, 5-28 combined)
    base_kernel<<<(NLEVEL + NCOMB) / ROWS_PER_BLK, 256, BASE_SMEM_BYTES>>>(
        level_tab, type_tab, feature_tab, exchange_tab, pair_tab, W, b);
    expand_kernel<<<4 * sm_count, 256>>>();

    // 6 blocks/SM x 256 threads = 48 warps/SM, no smem
    gather_kernel<<<6 * sm_count, 256>>>(level_idx, type_idx, feature_idx,
                                         exchange_idx, pair_idx,
                                         (float4*)d_out, n);
}